// round 11
// baseline (speedup 1.0000x reference)
#include <cuda_runtime.h>
#include <math.h>
#include <stdint.h>

// Problem constants
#define Bv 4
#define Sv 16
#define Nv 2048
#define Fv 32
#define Ev 16384
#define EFv 8
#define Hv 64
#define Lv 2
#define H2v 32
#define Gv (Bv*Sv)        // 64 graphs
#define SNv (Sv*Nv)       // 32768 GRU rows
#define E2v (Ev+Nv)       // 18432 edges incl self loops
#define GN (Gv*Nv)        // 131072 rows of X

// ---------------- scratch (static device globals; no allocation) ----------------
__device__ float g_X [GN*Hv];      // 33.5 MB  current node features [G][N][H]
__device__ float g_XL[GN*Hv];
__device__ float g_XR[GN*Hv];
__device__ float g_hg[GN*Hv];      // GAT output / GRU input
__device__ float g_ep[E2v*Hv];     // edge-attr projections
__device__ float g_logits[(size_t)Gv*E2v];
__device__ float g_loopattr[Nv*EFv];
__device__ int   g_deg[Nv];
__device__ int   g_rowstart[Nv+1];
__device__ int   g_cursor[Nv];
__device__ int   g_csr[Ev];
__device__ float g_Wpack[Lv*Hv*Hv*8];  // packed GRU weights [l][k][i][8]

// ---------------- preprocessing ----------------
__global__ void k_zero() {
    int idx = blockIdx.x*blockDim.x + threadIdx.x;
    if (idx < Nv) { g_deg[idx] = 0; g_cursor[idx] = 0; }
}

__global__ void k_deg(const int* __restrict__ ei) {
    int e = blockIdx.x*blockDim.x + threadIdx.x;
    if (e >= Ev) return;
    atomicAdd(&g_deg[ei[Ev + e]], 1);
}

__global__ void k_scan() {  // 1 block, 1024 threads: exclusive scan of deg -> rowstart
    __shared__ int s[1024];
    int t = threadIdx.x;
    int a = g_deg[2*t], b = g_deg[2*t+1];
    s[t] = a + b;
    __syncthreads();
    for (int off = 1; off < 1024; off <<= 1) {
        int v = (t >= off) ? s[t-off] : 0;
        __syncthreads();
        s[t] += v;
        __syncthreads();
    }
    int excl = s[t] - (a + b);
    g_rowstart[2*t]   = excl;
    g_rowstart[2*t+1] = excl + a;
    if (t == 1023) g_rowstart[2048] = s[1023];
}

__global__ void k_fill_csr(const int* __restrict__ ei) {
    int e = blockIdx.x*blockDim.x + threadIdx.x;
    if (e >= Ev) return;
    int d = ei[Ev + e];
    int pos = atomicAdd(&g_cursor[d], 1);
    g_csr[g_rowstart[d] + pos] = e;
}

// canonicalize CSR row order -> fully deterministic reduction order downstream
__global__ void k_sort_csr() {
    int n = blockIdx.x*blockDim.x + threadIdx.x;
    if (n >= Nv) return;
    int rs = g_rowstart[n], re = g_rowstart[n+1];
    for (int j = rs + 1; j < re; j++) {
        int v = g_csr[j];
        int k = j - 1;
        while (k >= rs && g_csr[k] > v) { g_csr[k+1] = g_csr[k]; k--; }
        g_csr[k+1] = v;
    }
}

// self-loop attr = mean of incoming edge attrs (deterministic: sorted CSR order)
__global__ void k_loopattr(const float* __restrict__ ea) {
    int idx = blockIdx.x*blockDim.x + threadIdx.x;   // Nv*EFv = 16384
    if (idx >= Nv*EFv) return;
    int n = idx >> 3, f = idx & 7;
    int rs = g_rowstart[n], re = g_rowstart[n+1];
    float s = 0.f;
    for (int j = rs; j < re; j++) s += ea[(size_t)g_csr[j]*EFv + f];
    g_loopattr[idx] = s / fmaxf((float)(re - rs), 1.f);
}

__global__ void k_pack_gru(const float* __restrict__ Wih, const float* __restrict__ Whh) {
    int idx = blockIdx.x*blockDim.x + threadIdx.x;   // L*H*H = 8192
    if (idx >= Lv*Hv*Hv) return;
    int l = idx >> 12, rem = idx & 4095, k = rem >> 6, i = rem & 63;
    float* dst = g_Wpack + (size_t)idx * 8;
    #pragma unroll
    for (int gate = 0; gate < 3; gate++) {
        dst[gate]   = Wih[l*192*64 + (gate*64 + i)*64 + k];
        dst[3+gate] = Whh[l*192*64 + (gate*64 + i)*64 + k];
    }
    dst[6] = 0.f; dst[7] = 0.f;
}

// ---------------- X = x @ Wp + bp  (32 rows/block, 8 rows/thread) ----------------
__global__ void k_proj(const float* __restrict__ x, const float* __restrict__ Wp,
                       const float* __restrict__ bp) {
    __shared__ float sW[Fv*Hv];      // 8 KB
    __shared__ float sx[32][Fv];     // 4 KB
    int tid = threadIdx.x;
    for (int j = tid; j < Fv*Hv; j += 256) sW[j] = Wp[j];
    size_t row0 = (size_t)blockIdx.x * 32;
    for (int j = tid; j < 32*Fv; j += 256) sx[j>>5][j&31] = x[row0*Fv + j];
    __syncthreads();
    int tr = tid >> 6, i = tid & 63;
    float bv = bp[i];
    float acc[8];
    #pragma unroll
    for (int r = 0; r < 8; r++) acc[r] = bv;
    for (int k = 0; k < Fv; k++) {
        float wv = sW[k*Hv + i];
        #pragma unroll
        for (int r = 0; r < 8; r++) acc[r] += sx[tr*8 + r][k] * wv;
    }
    #pragma unroll
    for (int r = 0; r < 8; r++) g_X[(row0 + tr*8 + r)*Hv + i] = acc[r];
}

// ---------------- XL/XR projections ----------------
// 32 rows/block; thread = (1 row, 8-output block) for both L and R.
// Inner loop k-vectorized: per k4 -> 1 LDS.128(x) + 16 LDS.128(w) + 64 FFMA.
__global__ void k_xlxr(const float* __restrict__ Wl, const float* __restrict__ bl,
                       const float* __restrict__ Wr, const float* __restrict__ br, int l) {
    __shared__ float sWl[Hv*Hv];     // 16 KB  (k-major: [k][i])
    __shared__ float sWr[Hv*Hv];     // 16 KB
    __shared__ float sx[32][68];     // padded rows, 16B-aligned stride
    int tid = threadIdx.x;
    for (int j = tid; j < Hv*Hv; j += 256) { sWl[j] = Wl[l*Hv*Hv + j]; sWr[j] = Wr[l*Hv*Hv + j]; }
    size_t row0 = (size_t)blockIdx.x * 32;
    for (int j = tid; j < 32*Hv; j += 256) sx[j>>6][j&63] = g_X[row0*Hv + j];
    __syncthreads();
    int tc = tid & 7, rr = tid >> 3;     // 8 output-blocks x 32 rows
    int i0 = tc * 8;
    float aL[8], aR[8];
    #pragma unroll
    for (int j = 0; j < 8; j++) { aL[j] = bl[l*Hv + i0 + j]; aR[j] = br[l*Hv + i0 + j]; }
    for (int k4 = 0; k4 < Hv; k4 += 4) {
        float4 xv = *(const float4*)&sx[rr][k4];
        float xa[4] = {xv.x, xv.y, xv.z, xv.w};
        #pragma unroll
        for (int kk = 0; kk < 4; kk++) {
            const float* wlrow = &sWl[(k4+kk)*Hv + i0];
            const float* wrrow = &sWr[(k4+kk)*Hv + i0];
            float4 wl0 = *(const float4*)wlrow;
            float4 wl1 = *(const float4*)(wlrow + 4);
            float4 wr0 = *(const float4*)wrrow;
            float4 wr1 = *(const float4*)(wrrow + 4);
            float xk = xa[kk];
            aL[0] += xk*wl0.x; aL[1] += xk*wl0.y; aL[2] += xk*wl0.z; aL[3] += xk*wl0.w;
            aL[4] += xk*wl1.x; aL[5] += xk*wl1.y; aL[6] += xk*wl1.z; aL[7] += xk*wl1.w;
            aR[0] += xk*wr0.x; aR[1] += xk*wr0.y; aR[2] += xk*wr0.z; aR[3] += xk*wr0.w;
            aR[4] += xk*wr1.x; aR[5] += xk*wr1.y; aR[6] += xk*wr1.z; aR[7] += xk*wr1.w;
        }
    }
    size_t base = (row0 + rr)*Hv + i0;
    *(float4*)&g_XL[base]     = make_float4(aL[0], aL[1], aL[2], aL[3]);
    *(float4*)&g_XL[base + 4] = make_float4(aL[4], aL[5], aL[6], aL[7]);
    *(float4*)&g_XR[base]     = make_float4(aR[0], aR[1], aR[2], aR[3]);
    *(float4*)&g_XR[base + 4] = make_float4(aR[4], aR[5], aR[6], aR[7]);
}

// ---------------- ep = ea_f @ We[l] ----------------
__global__ void k_ep(const float* __restrict__ ea, const float* __restrict__ We, int l) {
    int idx = blockIdx.x*blockDim.x + threadIdx.x;   // E2*H
    int e2 = idx >> 6, i = idx & 63;
    const float* a = (e2 < Ev) ? (ea + (size_t)e2*EFv) : (g_loopattr + (size_t)(e2 - Ev)*EFv);
    float acc = 0.f;
    #pragma unroll
    for (int f = 0; f < EFv; f++) acc += a[f] * We[l*EFv*Hv + f*Hv + i];
    g_ep[idx] = acc;
}

// ---------------- attention logits, warp per (g,e): edge-parallel ----------------
__global__ void k_logits(const int* __restrict__ ei, const float* __restrict__ att, int l) {
    int w = (blockIdx.x*blockDim.x + threadIdx.x) >> 5;
    int lane = threadIdx.x & 31;
    int g = w / E2v;
    int e = w - g*E2v;
    int sn, dn;
    if (e < Ev) { sn = ei[e]; dn = ei[Ev + e]; } else { sn = dn = e - Ev; }
    const float* xl = g_XL + ((size_t)g*Nv + sn)*Hv;
    const float* xr = g_XR + ((size_t)g*Nv + dn)*Hv;
    const float* ep = g_ep + (size_t)e*Hv;
    float acc = 0.f;
    #pragma unroll
    for (int c = 0; c < 2; c++) {
        int h = lane + 32*c;
        float m = xl[h] + xr[h] + ep[h];
        m = (m > 0.f) ? m : 0.2f*m;      // leaky_relu(0.2)
        acc += m * att[l*Hv + h];
    }
    #pragma unroll
    for (int o = 16; o; o >>= 1) acc += __shfl_xor_sync(0xffffffffu, acc, o);
    if (lane == 0) g_logits[(size_t)g*E2v + e] = acc;
}

// ---------------- softmax + aggregate, warp per (g,n) ----------------
__global__ void k_aggr(const int* __restrict__ ei, const float* __restrict__ gb, int l) {
    int w = (blockIdx.x*blockDim.x + threadIdx.x) >> 5;
    int lane = threadIdx.x & 31;
    int g = w >> 11;           // / N
    int n = w & (Nv-1);
    const float* lg = g_logits + (size_t)g*E2v;
    int rs = g_rowstart[n], re = g_rowstart[n+1];
    float lself = lg[Ev + n];
    float lmax = lself;
    for (int j = rs; j < re; j++) lmax = fmaxf(lmax, lg[g_csr[j]]);
    float psum, acc0, acc1;
    {
        float p = expf(lself - lmax);
        const float* xl = g_XL + ((size_t)g*Nv + n)*Hv;
        psum = p; acc0 = p*xl[lane]; acc1 = p*xl[lane+32];
    }
    for (int j = rs; j < re; j++) {
        int e = g_csr[j];
        int s = ei[e];
        float p = expf(lg[e] - lmax);
        const float* xl = g_XL + ((size_t)g*Nv + s)*Hv;
        psum += p; acc0 += p*xl[lane]; acc1 += p*xl[lane+32];
    }
    float inv = 1.f / psum;
    size_t o = ((size_t)g*Nv + n)*Hv;
    g_hg[o + lane]      = acc0*inv + gb[l*Hv + lane];
    g_hg[o + lane + 32] = acc1*inv + gb[l*Hv + lane + 32];
}

// ---------------- GRU layer: scan over T=B=4, 32 rows/block, h in shared ----------------
// k4-vectorized: per k4 per thread -> 8 broadcast LDS.128 (x,h) + 8 LDG.128 (w)
// + 96 FFMA  => FFMA pipe is the binding resource.
__global__ void __launch_bounds__(512) k_gru(const float* __restrict__ bih,
                                             const float* __restrict__ bhh, int l) {
    __shared__ float sx[32][Hv];
    __shared__ float sh[32][Hv];
    int tid = threadIdx.x;
    int tr = tid >> 6, i = tid & 63;    // 8 row-groups x 64 outputs
    int mb = blockIdx.x * 32;
    for (int r = tr; r < 32; r += 8) sh[r][i] = 0.f;
    float bi0 = bih[l*192 + i], bi1 = bih[l*192 + 64 + i], bi2 = bih[l*192 + 128 + i];
    float bh0 = bhh[l*192 + i], bh1 = bhh[l*192 + 64 + i], bh2 = bhh[l*192 + 128 + i];
    const float4* wrow = (const float4*)(g_Wpack + (size_t)l*Hv*Hv*8) + i*2;
    __syncthreads();
    for (int t = 0; t < Bv; t++) {
        for (int r = tr; r < 32; r += 8)
            sx[r][i] = g_hg[((size_t)t*SNv + mb + r)*Hv + i];
        __syncthreads();
        float a0[4], a1[4], a2[4], c0[4], c1[4], c2[4];
        #pragma unroll
        for (int r = 0; r < 4; r++) { a0[r]=bi0; a1[r]=bi1; a2[r]=bi2; c0[r]=bh0; c1[r]=bh1; c2[r]=bh2; }
        for (int k4 = 0; k4 < Hv; k4 += 4) {
            float4 xq[4], hq[4];
            #pragma unroll
            for (int r = 0; r < 4; r++) {
                int row = tr*4 + r;
                xq[r] = *(const float4*)&sx[row][k4];
                hq[r] = *(const float4*)&sh[row][k4];
            }
            #pragma unroll
            for (int kk = 0; kk < 4; kk++) {
                float4 wa = wrow[(k4+kk)*128];
                float4 wb = wrow[(k4+kk)*128 + 1];
                #pragma unroll
                for (int r = 0; r < 4; r++) {
                    float xv = ((const float*)&xq[r])[kk];
                    float hv = ((const float*)&hq[r])[kk];
                    a0[r] += xv*wa.x; a1[r] += xv*wa.y; a2[r] += xv*wa.z;
                    c0[r] += hv*wa.w; c1[r] += hv*wb.x; c2[r] += hv*wb.y;
                }
            }
        }
        float hnew[4];
        #pragma unroll
        for (int r = 0; r < 4; r++) {
            int row = tr*4 + r;
            float rg = 1.f / (1.f + expf(-(a0[r] + c0[r])));
            float zg = 1.f / (1.f + expf(-(a1[r] + c1[r])));
            float ng = tanhf(a2[r] + rg*c2[r]);
            hnew[r] = (1.f - zg)*ng + zg*sh[row][i];
        }
        __syncthreads();
        #pragma unroll
        for (int r = 0; r < 4; r++) {
            int row = tr*4 + r;
            sh[row][i] = hnew[r];
            g_X[((size_t)t*SNv + mb + row)*Hv + i] = hnew[r];
        }
        __syncthreads();
    }
}

// ---------------- output heads, warp per (b,n) row ----------------
__global__ void k_heads(const float* __restrict__ oW1, const float* __restrict__ ob1,
                        const float* __restrict__ oW2, const float* __restrict__ ob2,
                        const float* __restrict__ dW1, const float* __restrict__ db1,
                        const float* __restrict__ dW2, const float* __restrict__ db2,
                        float* __restrict__ out) {
    int w = (blockIdx.x*blockDim.x + threadIdx.x) >> 5;
    int lane = threadIdx.x & 31;
    int b = w >> 11, n = w & (Nv-1);
    const float* xl = g_X + (((size_t)(b*Sv + (Sv-1)))*Nv + n)*Hv;
    float x0 = xl[lane], x1 = xl[lane+32];
    float ho = ob1[lane], hd = db1[lane];
    for (int k = 0; k < Hv; k++) {
        float xv = __shfl_sync(0xffffffffu, (k < 32) ? x0 : x1, k & 31);
        ho += xv * oW1[k*H2v + lane];
        hd += xv * dW1[k*H2v + lane];
    }
    ho = fmaxf(ho, 0.f);
    hd = fmaxf(hd, 0.f);
    float so = ho * oW2[lane];
    float sd = hd * dW2[lane];
    #pragma unroll
    for (int o = 16; o; o >>= 1) {
        so += __shfl_xor_sync(0xffffffffu, so, o);
        sd += __shfl_xor_sync(0xffffffffu, sd, o);
    }
    if (lane == 0) {
        out[w]          = so + ob2[0];
        out[Bv*Nv + w]  = sd + db2[0];
    }
}

// ---------------- launcher ----------------
extern "C" void kernel_launch(void* const* d_in, const int* in_sizes, int n_in,
                              void* d_out, int out_size) {
    const float* x   = (const float*)d_in[0];
    const int*   ei  = (const int*)  d_in[1];
    const float* ea  = (const float*)d_in[2];
    const float* Wp  = (const float*)d_in[3];
    const float* bp  = (const float*)d_in[4];
    const float* Wl  = (const float*)d_in[5];
    const float* bl  = (const float*)d_in[6];
    const float* Wr  = (const float*)d_in[7];
    const float* br  = (const float*)d_in[8];
    const float* We  = (const float*)d_in[9];
    const float* att = (const float*)d_in[10];
    const float* gb  = (const float*)d_in[11];
    const float* Wih = (const float*)d_in[12];
    const float* Whh = (const float*)d_in[13];
    const float* bih = (const float*)d_in[14];
    const float* bhh = (const float*)d_in[15];
    const float* oW1 = (const float*)d_in[16];
    const float* ob1 = (const float*)d_in[17];
    const float* oW2 = (const float*)d_in[18];
    const float* ob2 = (const float*)d_in[19];
    const float* dW1 = (const float*)d_in[20];
    const float* db1 = (const float*)d_in[21];
    const float* dW2 = (const float*)d_in[22];
    const float* db2 = (const float*)d_in[23];
    float* out = (float*)d_out;

    // preprocessing (deterministic CSR + loop attrs)
    k_zero    <<<8, 256>>>();
    k_deg     <<<64, 256>>>(ei);
    k_scan    <<<1, 1024>>>();
    k_fill_csr<<<64, 256>>>(ei);
    k_sort_csr<<<8, 256>>>();
    k_loopattr<<<64, 256>>>(ea);
    k_pack_gru<<<32, 256>>>(Wih, Whh);

    // input projection
    k_proj<<<GN/32, 256>>>(x, Wp, bp);

    for (int l = 0; l < Lv; l++) {
        k_xlxr  <<<GN/32, 256>>>(Wl, bl, Wr, br, l);
        k_ep    <<<E2v*Hv/256, 256>>>(ea, We, l);
        k_logits<<<(int)((size_t)Gv*E2v*32/256), 256>>>(ei, att, l);
        k_aggr  <<<GN*32/256, 256>>>(ei, gb, l);
        k_gru   <<<SNv/32, 512>>>(bih, bhh, l);
    }

    k_heads<<<Bv*Nv*32/256, 256>>>(oW1, ob1, oW2, ob2, dW1, db1, dW2, db2, out);
}

// round 12
// speedup vs baseline: 1.5672x; 1.5672x over previous
#include <cuda_runtime.h>
#include <math.h>
#include <stdint.h>

// Problem constants
#define Bv 4
#define Sv 16
#define Nv 2048
#define Fv 32
#define Ev 16384
#define EFv 8
#define Hv 64
#define Lv 2
#define H2v 32
#define Gv (Bv*Sv)        // 64 graphs
#define SNv (Sv*Nv)       // 32768 GRU rows
#define E2v (Ev+Nv)       // 18432 edges incl self loops
#define GN (Gv*Nv)        // 131072 rows of X

// ---------------- scratch (static device globals; no allocation) ----------------
__device__ float g_X [GN*Hv];      // 33.5 MB  current node features [G][N][H]
__device__ float g_XL[GN*Hv];
__device__ float g_XR[GN*Hv];
__device__ float g_hg[GN*Hv];      // GAT output / GRU input
__device__ float g_ep[E2v*Hv];     // edge-attr projections
__device__ float g_logits[(size_t)Gv*E2v];
__device__ float g_loopattr[Nv*EFv];
__device__ int   g_deg[Nv];
__device__ int   g_rowstart[Nv+1];
__device__ int   g_cursor[Nv];
__device__ int   g_csr[Ev];
__device__ float g_Wpack[Lv*Hv*6*Hv];  // GRU weights [l][k][slot][i], slot=(ir,iz,in,hr,hz,hn)

// ---------------- preprocessing ----------------
__global__ void k_zero() {
    int idx = blockIdx.x*blockDim.x + threadIdx.x;
    if (idx < Nv) { g_deg[idx] = 0; g_cursor[idx] = 0; }
}

__global__ void k_deg(const int* __restrict__ ei) {
    int e = blockIdx.x*blockDim.x + threadIdx.x;
    if (e >= Ev) return;
    atomicAdd(&g_deg[ei[Ev + e]], 1);
}

__global__ void k_scan() {  // 1 block, 1024 threads: exclusive scan of deg -> rowstart
    __shared__ int s[1024];
    int t = threadIdx.x;
    int a = g_deg[2*t], b = g_deg[2*t+1];
    s[t] = a + b;
    __syncthreads();
    for (int off = 1; off < 1024; off <<= 1) {
        int v = (t >= off) ? s[t-off] : 0;
        __syncthreads();
        s[t] += v;
        __syncthreads();
    }
    int excl = s[t] - (a + b);
    g_rowstart[2*t]   = excl;
    g_rowstart[2*t+1] = excl + a;
    if (t == 1023) g_rowstart[2048] = s[1023];
}

__global__ void k_fill_csr(const int* __restrict__ ei) {
    int e = blockIdx.x*blockDim.x + threadIdx.x;
    if (e >= Ev) return;
    int d = ei[Ev + e];
    int pos = atomicAdd(&g_cursor[d], 1);
    g_csr[g_rowstart[d] + pos] = e;
}

// canonicalize CSR row order -> fully deterministic reduction order downstream
__global__ void k_sort_csr() {
    int n = blockIdx.x*blockDim.x + threadIdx.x;
    if (n >= Nv) return;
    int rs = g_rowstart[n], re = g_rowstart[n+1];
    for (int j = rs + 1; j < re; j++) {
        int v = g_csr[j];
        int k = j - 1;
        while (k >= rs && g_csr[k] > v) { g_csr[k+1] = g_csr[k]; k--; }
        g_csr[k+1] = v;
    }
}

// self-loop attr = mean of incoming edge attrs (deterministic: sorted CSR order)
__global__ void k_loopattr(const float* __restrict__ ea) {
    int idx = blockIdx.x*blockDim.x + threadIdx.x;   // Nv*EFv = 16384
    if (idx >= Nv*EFv) return;
    int n = idx >> 3, f = idx & 7;
    int rs = g_rowstart[n], re = g_rowstart[n+1];
    float s = 0.f;
    for (int j = rs; j < re; j++) s += ea[(size_t)g_csr[j]*EFv + f];
    g_loopattr[idx] = s / fmaxf((float)(re - rs), 1.f);
}

// pack GRU weights k-major with i contiguous per slot: [l][k][slot][i]
__global__ void k_pack_gru(const float* __restrict__ Wih, const float* __restrict__ Whh) {
    int idx = blockIdx.x*blockDim.x + threadIdx.x;   // L*H*H = 8192
    if (idx >= Lv*Hv*Hv) return;
    int l = idx >> 12, rem = idx & 4095, k = rem >> 6, i = rem & 63;
    float* dst = g_Wpack + (((size_t)l*Hv + k)*6)*Hv + i;
    #pragma unroll
    for (int gate = 0; gate < 3; gate++) {
        dst[gate*Hv]       = Wih[l*192*64 + (gate*64 + i)*64 + k];
        dst[(3+gate)*Hv]   = Whh[l*192*64 + (gate*64 + i)*64 + k];
    }
}

// ---------------- X = x @ Wp + bp  (32 rows/block, 8 rows/thread) ----------------
__global__ void k_proj(const float* __restrict__ x, const float* __restrict__ Wp,
                       const float* __restrict__ bp) {
    __shared__ float sW[Fv*Hv];      // 8 KB
    __shared__ float sx[32][Fv];     // 4 KB
    int tid = threadIdx.x;
    for (int j = tid; j < Fv*Hv; j += 256) sW[j] = Wp[j];
    size_t row0 = (size_t)blockIdx.x * 32;
    for (int j = tid; j < 32*Fv; j += 256) sx[j>>5][j&31] = x[row0*Fv + j];
    __syncthreads();
    int tr = tid >> 6, i = tid & 63;
    float bv = bp[i];
    float acc[8];
    #pragma unroll
    for (int r = 0; r < 8; r++) acc[r] = bv;
    for (int k = 0; k < Fv; k++) {
        float wv = sW[k*Hv + i];
        #pragma unroll
        for (int r = 0; r < 8; r++) acc[r] += sx[tr*8 + r][k] * wv;
    }
    #pragma unroll
    for (int r = 0; r < 8; r++) g_X[(row0 + tr*8 + r)*Hv + i] = acc[r];
}

// ---------------- XL/XR projections (R7 baseline: 32 rows/block, 8 rows/thread) ----------------
__global__ void k_xlxr(const float* __restrict__ Wl, const float* __restrict__ bl,
                       const float* __restrict__ Wr, const float* __restrict__ br, int l) {
    __shared__ float sWl[Hv*Hv];     // 16 KB
    __shared__ float sWr[Hv*Hv];     // 16 KB
    __shared__ float sx[32][Hv];     // 8 KB
    int tid = threadIdx.x;
    for (int j = tid; j < Hv*Hv; j += 256) { sWl[j] = Wl[l*Hv*Hv + j]; sWr[j] = Wr[l*Hv*Hv + j]; }
    size_t row0 = (size_t)blockIdx.x * 32;
    for (int j = tid; j < 32*Hv; j += 256) sx[j>>6][j&63] = g_X[row0*Hv + j];
    __syncthreads();
    int tr = tid >> 6, i = tid & 63;
    float blv = bl[l*Hv + i], brv = br[l*Hv + i];
    float aL[8], aR[8];
    #pragma unroll
    for (int r = 0; r < 8; r++) { aL[r] = blv; aR[r] = brv; }
    for (int k = 0; k < Hv; k++) {
        float wl = sWl[k*Hv + i], wr = sWr[k*Hv + i];
        #pragma unroll
        for (int r = 0; r < 8; r++) {
            float xv = sx[tr*8 + r][k];
            aL[r] += xv * wl;
            aR[r] += xv * wr;
        }
    }
    #pragma unroll
    for (int r = 0; r < 8; r++) {
        size_t row = row0 + tr*8 + r;
        g_XL[row*Hv + i] = aL[r];
        g_XR[row*Hv + i] = aR[r];
    }
}

// ---------------- ep = ea_f @ We[l] ----------------
__global__ void k_ep(const float* __restrict__ ea, const float* __restrict__ We, int l) {
    int idx = blockIdx.x*blockDim.x + threadIdx.x;   // E2*H
    int e2 = idx >> 6, i = idx & 63;
    const float* a = (e2 < Ev) ? (ea + (size_t)e2*EFv) : (g_loopattr + (size_t)(e2 - Ev)*EFv);
    float acc = 0.f;
    #pragma unroll
    for (int f = 0; f < EFv; f++) acc += a[f] * We[l*EFv*Hv + f*Hv + i];
    g_ep[idx] = acc;
}

// ---------------- attention logits, warp per (g,e): edge-parallel ----------------
__global__ void k_logits(const int* __restrict__ ei, const float* __restrict__ att, int l) {
    int w = (blockIdx.x*blockDim.x + threadIdx.x) >> 5;
    int lane = threadIdx.x & 31;
    int g = w / E2v;
    int e = w - g*E2v;
    int sn, dn;
    if (e < Ev) { sn = ei[e]; dn = ei[Ev + e]; } else { sn = dn = e - Ev; }
    const float* xl = g_XL + ((size_t)g*Nv + sn)*Hv;
    const float* xr = g_XR + ((size_t)g*Nv + dn)*Hv;
    const float* ep = g_ep + (size_t)e*Hv;
    float acc = 0.f;
    #pragma unroll
    for (int c = 0; c < 2; c++) {
        int h = lane + 32*c;
        float m = xl[h] + xr[h] + ep[h];
        m = (m > 0.f) ? m : 0.2f*m;      // leaky_relu(0.2)
        acc += m * att[l*Hv + h];
    }
    #pragma unroll
    for (int o = 16; o; o >>= 1) acc += __shfl_xor_sync(0xffffffffu, acc, o);
    if (lane == 0) g_logits[(size_t)g*E2v + e] = acc;
}

// ---------------- softmax + aggregate, warp per (g,n) ----------------
__global__ void k_aggr(const int* __restrict__ ei, const float* __restrict__ gb, int l) {
    int w = (blockIdx.x*blockDim.x + threadIdx.x) >> 5;
    int lane = threadIdx.x & 31;
    int g = w >> 11;           // / N
    int n = w & (Nv-1);
    const float* lg = g_logits + (size_t)g*E2v;
    int rs = g_rowstart[n], re = g_rowstart[n+1];
    float lself = lg[Ev + n];
    float lmax = lself;
    for (int j = rs; j < re; j++) lmax = fmaxf(lmax, lg[g_csr[j]]);
    float psum, acc0, acc1;
    {
        float p = expf(lself - lmax);
        const float* xl = g_XL + ((size_t)g*Nv + n)*Hv;
        psum = p; acc0 = p*xl[lane]; acc1 = p*xl[lane+32];
    }
    for (int j = rs; j < re; j++) {
        int e = g_csr[j];
        int s = ei[e];
        float p = expf(lg[e] - lmax);
        const float* xl = g_XL + ((size_t)g*Nv + s)*Hv;
        psum += p; acc0 += p*xl[lane]; acc1 += p*xl[lane+32];
    }
    float inv = 1.f / psum;
    size_t o = ((size_t)g*Nv + n)*Hv;
    g_hg[o + lane]      = acc0*inv + gb[l*Hv + lane];
    g_hg[o + lane + 32] = acc1*inv + gb[l*Hv + lane + 32];
}

// ---------------- GRU layer: scan over T=B=4, 16 rows/block ----------------
// v3: coalesced scalar weight loads ([k][slot][i] layout: 6 x 128B wavefronts per k
// per warp, L1-resident 96KB/layer) + broadcast LDS.128 for x/h (2 wf per k4).
// L1 wavefronts/k: 8 -> FFMA (48 SMSP-cyc/k) is now the binding pipe.
__global__ void k_gru(const float* __restrict__ bih, const float* __restrict__ bhh, int l) {
    __shared__ float sx[16][Hv];
    __shared__ float sh[16][Hv];
    int tid = threadIdx.x;
    int tr = tid >> 6, i = tid & 63;
    int mb = blockIdx.x * 16;
    for (int r = tr; r < 16; r += 4) sh[r][i] = 0.f;
    float bi0 = bih[l*192 + i], bi1 = bih[l*192 + 64 + i], bi2 = bih[l*192 + 128 + i];
    float bh0 = bhh[l*192 + i], bh1 = bhh[l*192 + 64 + i], bh2 = bhh[l*192 + 128 + i];
    const float* __restrict__ wbase = g_Wpack + (size_t)l*Hv*6*Hv + i;
    __syncthreads();
    for (int t = 0; t < Bv; t++) {
        for (int r = tr; r < 16; r += 4)
            sx[r][i] = g_hg[((size_t)t*SNv + mb + r)*Hv + i];
        __syncthreads();
        float a0[4], a1[4], a2[4], c0[4], c1[4], c2[4];
        #pragma unroll
        for (int r = 0; r < 4; r++) { a0[r]=bi0; a1[r]=bi1; a2[r]=bi2; c0[r]=bh0; c1[r]=bh1; c2[r]=bh2; }
        for (int k4 = 0; k4 < Hv; k4 += 4) {
            float4 xq[4], hq[4];
            #pragma unroll
            for (int r = 0; r < 4; r++) {
                int row = tr*4 + r;
                xq[r] = *(const float4*)&sx[row][k4];
                hq[r] = *(const float4*)&sh[row][k4];
            }
            #pragma unroll
            for (int kk = 0; kk < 4; kk++) {
                const float* w = wbase + (size_t)(k4+kk)*6*Hv;
                float w0 = w[0],      w1 = w[Hv],     w2 = w[2*Hv];
                float w3 = w[3*Hv],   w4 = w[4*Hv],   w5 = w[5*Hv];
                #pragma unroll
                for (int r = 0; r < 4; r++) {
                    float xv = ((const float*)&xq[r])[kk];
                    float hv = ((const float*)&hq[r])[kk];
                    a0[r] += xv*w0; a1[r] += xv*w1; a2[r] += xv*w2;
                    c0[r] += hv*w3; c1[r] += hv*w4; c2[r] += hv*w5;
                }
            }
        }
        float hnew[4];
        #pragma unroll
        for (int r = 0; r < 4; r++) {
            int row = tr*4 + r;
            float rg = 1.f / (1.f + expf(-(a0[r] + c0[r])));
            float zg = 1.f / (1.f + expf(-(a1[r] + c1[r])));
            float ng = tanhf(a2[r] + rg*c2[r]);
            hnew[r] = (1.f - zg)*ng + zg*sh[row][i];
        }
        __syncthreads();
        #pragma unroll
        for (int r = 0; r < 4; r++) {
            int row = tr*4 + r;
            sh[row][i] = hnew[r];
            g_X[((size_t)t*SNv + mb + row)*Hv + i] = hnew[r];
        }
        __syncthreads();
    }
}

// ---------------- output heads, warp per (b,n) row ----------------
__global__ void k_heads(const float* __restrict__ oW1, const float* __restrict__ ob1,
                        const float* __restrict__ oW2, const float* __restrict__ ob2,
                        const float* __restrict__ dW1, const float* __restrict__ db1,
                        const float* __restrict__ dW2, const float* __restrict__ db2,
                        float* __restrict__ out) {
    int w = (blockIdx.x*blockDim.x + threadIdx.x) >> 5;
    int lane = threadIdx.x & 31;
    int b = w >> 11, n = w & (Nv-1);
    const float* xl = g_X + (((size_t)(b*Sv + (Sv-1)))*Nv + n)*Hv;
    float x0 = xl[lane], x1 = xl[lane+32];
    float ho = ob1[lane], hd = db1[lane];
    for (int k = 0; k < Hv; k++) {
        float xv = __shfl_sync(0xffffffffu, (k < 32) ? x0 : x1, k & 31);
        ho += xv * oW1[k*H2v + lane];
        hd += xv * dW1[k*H2v + lane];
    }
    ho = fmaxf(ho, 0.f);
    hd = fmaxf(hd, 0.f);
    float so = ho * oW2[lane];
    float sd = hd * dW2[lane];
    #pragma unroll
    for (int o = 16; o; o >>= 1) {
        so += __shfl_xor_sync(0xffffffffu, so, o);
        sd += __shfl_xor_sync(0xffffffffu, sd, o);
    }
    if (lane == 0) {
        out[w]          = so + ob2[0];
        out[Bv*Nv + w]  = sd + db2[0];
    }
}

// ---------------- launcher ----------------
extern "C" void kernel_launch(void* const* d_in, const int* in_sizes, int n_in,
                              void* d_out, int out_size) {
    const float* x   = (const float*)d_in[0];
    const int*   ei  = (const int*)  d_in[1];
    const float* ea  = (const float*)d_in[2];
    const float* Wp  = (const float*)d_in[3];
    const float* bp  = (const float*)d_in[4];
    const float* Wl  = (const float*)d_in[5];
    const float* bl  = (const float*)d_in[6];
    const float* Wr  = (const float*)d_in[7];
    const float* br  = (const float*)d_in[8];
    const float* We  = (const float*)d_in[9];
    const float* att = (const float*)d_in[10];
    const float* gb  = (const float*)d_in[11];
    const float* Wih = (const float*)d_in[12];
    const float* Whh = (const float*)d_in[13];
    const float* bih = (const float*)d_in[14];
    const float* bhh = (const float*)d_in[15];
    const float* oW1 = (const float*)d_in[16];
    const float* ob1 = (const float*)d_in[17];
    const float* oW2 = (const float*)d_in[18];
    const float* ob2 = (const float*)d_in[19];
    const float* dW1 = (const float*)d_in[20];
    const float* db1 = (const float*)d_in[21];
    const float* dW2 = (const float*)d_in[22];
    const float* db2 = (const float*)d_in[23];
    float* out = (float*)d_out;

    // preprocessing (deterministic CSR + loop attrs)
    k_zero    <<<8, 256>>>();
    k_deg     <<<64, 256>>>(ei);
    k_scan    <<<1, 1024>>>();
    k_fill_csr<<<64, 256>>>(ei);
    k_sort_csr<<<8, 256>>>();
    k_loopattr<<<64, 256>>>(ea);
    k_pack_gru<<<32, 256>>>(Wih, Whh);

    // input projection
    k_proj<<<GN/32, 256>>>(x, Wp, bp);

    for (int l = 0; l < Lv; l++) {
        k_xlxr  <<<GN/32, 256>>>(Wl, bl, Wr, br, l);
        k_ep    <<<E2v*Hv/256, 256>>>(ea, We, l);
        k_logits<<<(int)((size_t)Gv*E2v*32/256), 256>>>(ei, att, l);
        k_aggr  <<<GN*32/256, 256>>>(ei, gb, l);
        k_gru   <<<SNv/16, 256>>>(bih, bhh, l);
    }

    k_heads<<<Bv*Nv*32/256, 256>>>(oW1, ob1, oW2, ob2, dW1, db1, dW2, db2, out);
}

// round 13
// speedup vs baseline: 1.5678x; 1.0004x over previous
#include <cuda_runtime.h>
#include <math.h>
#include <stdint.h>

// Problem constants
#define Bv 4
#define Sv 16
#define Nv 2048
#define Fv 32
#define Ev 16384
#define EFv 8
#define Hv 64
#define Lv 2
#define H2v 32
#define Gv (Bv*Sv)        // 64 graphs
#define SNv (Sv*Nv)       // 32768 GRU rows
#define E2v (Ev+Nv)       // 18432 edges incl self loops
#define GN (Gv*Nv)        // 131072 rows of X

// ---------------- scratch (static device globals; no allocation) ----------------
__device__ float g_X [GN*Hv];      // 33.5 MB  current node features [G][N][H]
__device__ float g_XL[GN*Hv];
__device__ float g_XR[GN*Hv];
__device__ float g_hg[GN*Hv];      // GAT output / GRU input
__device__ float g_ep[E2v*Hv];     // edge-attr projections
__device__ float g_logits[(size_t)Gv*E2v];
__device__ float g_loopattr[Nv*EFv];
__device__ int   g_deg[Nv];
__device__ int   g_rowstart[Nv+1];
__device__ int   g_cursor[Nv];
__device__ int   g_csr[Ev];
__device__ float g_Wpack[Lv*Hv*6*Hv];  // GRU weights [l][k][slot][i], slot=(ir,iz,in,hr,hz,hn)

// ---------------- preprocessing ----------------
__global__ void k_zero() {
    int idx = blockIdx.x*blockDim.x + threadIdx.x;
    if (idx < Nv) { g_deg[idx] = 0; g_cursor[idx] = 0; }
}

__global__ void k_deg(const int* __restrict__ ei) {
    int e = blockIdx.x*blockDim.x + threadIdx.x;
    if (e >= Ev) return;
    atomicAdd(&g_deg[ei[Ev + e]], 1);
}

__global__ void k_scan() {  // 1 block, 1024 threads: exclusive scan of deg -> rowstart
    __shared__ int s[1024];
    int t = threadIdx.x;
    int a = g_deg[2*t], b = g_deg[2*t+1];
    s[t] = a + b;
    __syncthreads();
    for (int off = 1; off < 1024; off <<= 1) {
        int v = (t >= off) ? s[t-off] : 0;
        __syncthreads();
        s[t] += v;
        __syncthreads();
    }
    int excl = s[t] - (a + b);
    g_rowstart[2*t]   = excl;
    g_rowstart[2*t+1] = excl + a;
    if (t == 1023) g_rowstart[2048] = s[1023];
}

__global__ void k_fill_csr(const int* __restrict__ ei) {
    int e = blockIdx.x*blockDim.x + threadIdx.x;
    if (e >= Ev) return;
    int d = ei[Ev + e];
    int pos = atomicAdd(&g_cursor[d], 1);
    g_csr[g_rowstart[d] + pos] = e;
}

// canonicalize CSR row order -> fully deterministic reduction order downstream
__global__ void k_sort_csr() {
    int n = blockIdx.x*blockDim.x + threadIdx.x;
    if (n >= Nv) return;
    int rs = g_rowstart[n], re = g_rowstart[n+1];
    for (int j = rs + 1; j < re; j++) {
        int v = g_csr[j];
        int k = j - 1;
        while (k >= rs && g_csr[k] > v) { g_csr[k+1] = g_csr[k]; k--; }
        g_csr[k+1] = v;
    }
}

// self-loop attr = mean of incoming edge attrs (deterministic: sorted CSR order)
__global__ void k_loopattr(const float* __restrict__ ea) {
    int idx = blockIdx.x*blockDim.x + threadIdx.x;   // Nv*EFv = 16384
    if (idx >= Nv*EFv) return;
    int n = idx >> 3, f = idx & 7;
    int rs = g_rowstart[n], re = g_rowstart[n+1];
    float s = 0.f;
    for (int j = rs; j < re; j++) s += ea[(size_t)g_csr[j]*EFv + f];
    g_loopattr[idx] = s / fmaxf((float)(re - rs), 1.f);
}

// pack GRU weights k-major with i contiguous per slot: [l][k][slot][i]
__global__ void k_pack_gru(const float* __restrict__ Wih, const float* __restrict__ Whh) {
    int idx = blockIdx.x*blockDim.x + threadIdx.x;   // L*H*H = 8192
    if (idx >= Lv*Hv*Hv) return;
    int l = idx >> 12, rem = idx & 4095, k = rem >> 6, i = rem & 63;
    float* dst = g_Wpack + (((size_t)l*Hv + k)*6)*Hv + i;
    #pragma unroll
    for (int gate = 0; gate < 3; gate++) {
        dst[gate*Hv]       = Wih[l*192*64 + (gate*64 + i)*64 + k];
        dst[(3+gate)*Hv]   = Whh[l*192*64 + (gate*64 + i)*64 + k];
    }
}

// ---------------- X = x @ Wp + bp  (32 rows/block, 8 rows/thread) ----------------
__global__ void k_proj(const float* __restrict__ x, const float* __restrict__ Wp,
                       const float* __restrict__ bp) {
    __shared__ float sW[Fv*Hv];      // 8 KB
    __shared__ float sx[32][Fv];     // 4 KB
    int tid = threadIdx.x;
    for (int j = tid; j < Fv*Hv; j += 256) sW[j] = Wp[j];
    size_t row0 = (size_t)blockIdx.x * 32;
    for (int j = tid; j < 32*Fv; j += 256) sx[j>>5][j&31] = x[row0*Fv + j];
    __syncthreads();
    int tr = tid >> 6, i = tid & 63;
    float bv = bp[i];
    float acc[8];
    #pragma unroll
    for (int r = 0; r < 8; r++) acc[r] = bv;
    for (int k = 0; k < Fv; k++) {
        float wv = sW[k*Hv + i];
        #pragma unroll
        for (int r = 0; r < 8; r++) acc[r] += sx[tr*8 + r][k] * wv;
    }
    #pragma unroll
    for (int r = 0; r < 8; r++) g_X[(row0 + tr*8 + r)*Hv + i] = acc[r];
}

// ---------------- XL/XR projections (v3) ----------------
// v1 mapping (thread = one i column x 8 rows; identical accumulation order),
// but sx hoisted to float4 registers per k4: per k4 per warp ->
// 8 broadcast LDS.128 (x) + 8 coalesced scalar w LDS = 16 wf vs 64 FFMA.
__global__ void k_xlxr(const float* __restrict__ Wl, const float* __restrict__ bl,
                       const float* __restrict__ Wr, const float* __restrict__ br, int l) {
    __shared__ float sWl[Hv*Hv];     // 16 KB
    __shared__ float sWr[Hv*Hv];     // 16 KB
    __shared__ float sx[32][Hv];     // 8 KB
    int tid = threadIdx.x;
    for (int j = tid; j < Hv*Hv; j += 256) { sWl[j] = Wl[l*Hv*Hv + j]; sWr[j] = Wr[l*Hv*Hv + j]; }
    size_t row0 = (size_t)blockIdx.x * 32;
    for (int j = tid; j < 32*Hv; j += 256) sx[j>>6][j&63] = g_X[row0*Hv + j];
    __syncthreads();
    int tr = tid >> 6, i = tid & 63;
    float blv = bl[l*Hv + i], brv = br[l*Hv + i];
    float aL[8], aR[8];
    #pragma unroll
    for (int r = 0; r < 8; r++) { aL[r] = blv; aR[r] = brv; }
    for (int k4 = 0; k4 < Hv; k4 += 4) {
        float4 xq[8];
        #pragma unroll
        for (int r = 0; r < 8; r++) xq[r] = *(const float4*)&sx[tr*8 + r][k4];
        #pragma unroll
        for (int kk = 0; kk < 4; kk++) {
            float wl = sWl[(k4+kk)*Hv + i], wr = sWr[(k4+kk)*Hv + i];
            #pragma unroll
            for (int r = 0; r < 8; r++) {
                float xv = ((const float*)&xq[r])[kk];
                aL[r] += xv * wl;
                aR[r] += xv * wr;
            }
        }
    }
    #pragma unroll
    for (int r = 0; r < 8; r++) {
        size_t row = row0 + tr*8 + r;
        g_XL[row*Hv + i] = aL[r];
        g_XR[row*Hv + i] = aR[r];
    }
}

// ---------------- ep = ea_f @ We[l] ----------------
__global__ void k_ep(const float* __restrict__ ea, const float* __restrict__ We, int l) {
    int idx = blockIdx.x*blockDim.x + threadIdx.x;   // E2*H
    int e2 = idx >> 6, i = idx & 63;
    const float* a = (e2 < Ev) ? (ea + (size_t)e2*EFv) : (g_loopattr + (size_t)(e2 - Ev)*EFv);
    float acc = 0.f;
    #pragma unroll
    for (int f = 0; f < EFv; f++) acc += a[f] * We[l*EFv*Hv + f*Hv + i];
    g_ep[idx] = acc;
}

// ---------------- attention logits, warp per (g,e): edge-parallel ----------------
__global__ void k_logits(const int* __restrict__ ei, const float* __restrict__ att, int l) {
    int w = (blockIdx.x*blockDim.x + threadIdx.x) >> 5;
    int lane = threadIdx.x & 31;
    int g = w / E2v;
    int e = w - g*E2v;
    int sn, dn;
    if (e < Ev) { sn = ei[e]; dn = ei[Ev + e]; } else { sn = dn = e - Ev; }
    const float* xl = g_XL + ((size_t)g*Nv + sn)*Hv;
    const float* xr = g_XR + ((size_t)g*Nv + dn)*Hv;
    const float* ep = g_ep + (size_t)e*Hv;
    float acc = 0.f;
    #pragma unroll
    for (int c = 0; c < 2; c++) {
        int h = lane + 32*c;
        float m = xl[h] + xr[h] + ep[h];
        m = (m > 0.f) ? m : 0.2f*m;      // leaky_relu(0.2)
        acc += m * att[l*Hv + h];
    }
    #pragma unroll
    for (int o = 16; o; o >>= 1) acc += __shfl_xor_sync(0xffffffffu, acc, o);
    if (lane == 0) g_logits[(size_t)g*E2v + e] = acc;
}

// ---------------- softmax + aggregate, warp per (g,n) ----------------
__global__ void k_aggr(const int* __restrict__ ei, const float* __restrict__ gb, int l) {
    int w = (blockIdx.x*blockDim.x + threadIdx.x) >> 5;
    int lane = threadIdx.x & 31;
    int g = w >> 11;           // / N
    int n = w & (Nv-1);
    const float* lg = g_logits + (size_t)g*E2v;
    int rs = g_rowstart[n], re = g_rowstart[n+1];
    float lself = lg[Ev + n];
    float lmax = lself;
    for (int j = rs; j < re; j++) lmax = fmaxf(lmax, lg[g_csr[j]]);
    float psum, acc0, acc1;
    {
        float p = expf(lself - lmax);
        const float* xl = g_XL + ((size_t)g*Nv + n)*Hv;
        psum = p; acc0 = p*xl[lane]; acc1 = p*xl[lane+32];
    }
    for (int j = rs; j < re; j++) {
        int e = g_csr[j];
        int s = ei[e];
        float p = expf(lg[e] - lmax);
        const float* xl = g_XL + ((size_t)g*Nv + s)*Hv;
        psum += p; acc0 += p*xl[lane]; acc1 += p*xl[lane+32];
    }
    float inv = 1.f / psum;
    size_t o = ((size_t)g*Nv + n)*Hv;
    g_hg[o + lane]      = acc0*inv + gb[l*Hv + lane];
    g_hg[o + lane + 32] = acc1*inv + gb[l*Hv + lane + 32];
}

// ---------------- GRU layer: scan over T=B=4, 16 rows/block ----------------
// v3 (confirmed win): coalesced scalar weight loads ([k][slot][i]) +
// broadcast LDS.128 for x/h -> FFMA-bound.
__global__ void k_gru(const float* __restrict__ bih, const float* __restrict__ bhh, int l) {
    __shared__ float sx[16][Hv];
    __shared__ float sh[16][Hv];
    int tid = threadIdx.x;
    int tr = tid >> 6, i = tid & 63;
    int mb = blockIdx.x * 16;
    for (int r = tr; r < 16; r += 4) sh[r][i] = 0.f;
    float bi0 = bih[l*192 + i], bi1 = bih[l*192 + 64 + i], bi2 = bih[l*192 + 128 + i];
    float bh0 = bhh[l*192 + i], bh1 = bhh[l*192 + 64 + i], bh2 = bhh[l*192 + 128 + i];
    const float* __restrict__ wbase = g_Wpack + (size_t)l*Hv*6*Hv + i;
    __syncthreads();
    for (int t = 0; t < Bv; t++) {
        for (int r = tr; r < 16; r += 4)
            sx[r][i] = g_hg[((size_t)t*SNv + mb + r)*Hv + i];
        __syncthreads();
        float a0[4], a1[4], a2[4], c0[4], c1[4], c2[4];
        #pragma unroll
        for (int r = 0; r < 4; r++) { a0[r]=bi0; a1[r]=bi1; a2[r]=bi2; c0[r]=bh0; c1[r]=bh1; c2[r]=bh2; }
        for (int k4 = 0; k4 < Hv; k4 += 4) {
            float4 xq[4], hq[4];
            #pragma unroll
            for (int r = 0; r < 4; r++) {
                int row = tr*4 + r;
                xq[r] = *(const float4*)&sx[row][k4];
                hq[r] = *(const float4*)&sh[row][k4];
            }
            #pragma unroll
            for (int kk = 0; kk < 4; kk++) {
                const float* w = wbase + (size_t)(k4+kk)*6*Hv;
                float w0 = w[0],      w1 = w[Hv],     w2 = w[2*Hv];
                float w3 = w[3*Hv],   w4 = w[4*Hv],   w5 = w[5*Hv];
                #pragma unroll
                for (int r = 0; r < 4; r++) {
                    float xv = ((const float*)&xq[r])[kk];
                    float hv = ((const float*)&hq[r])[kk];
                    a0[r] += xv*w0; a1[r] += xv*w1; a2[r] += xv*w2;
                    c0[r] += hv*w3; c1[r] += hv*w4; c2[r] += hv*w5;
                }
            }
        }
        float hnew[4];
        #pragma unroll
        for (int r = 0; r < 4; r++) {
            int row = tr*4 + r;
            float rg = 1.f / (1.f + expf(-(a0[r] + c0[r])));
            float zg = 1.f / (1.f + expf(-(a1[r] + c1[r])));
            float ng = tanhf(a2[r] + rg*c2[r]);
            hnew[r] = (1.f - zg)*ng + zg*sh[row][i];
        }
        __syncthreads();
        #pragma unroll
        for (int r = 0; r < 4; r++) {
            int row = tr*4 + r;
            sh[row][i] = hnew[r];
            g_X[((size_t)t*SNv + mb + row)*Hv + i] = hnew[r];
        }
        __syncthreads();
    }
}

// ---------------- output heads, warp per (b,n) row ----------------
__global__ void k_heads(const float* __restrict__ oW1, const float* __restrict__ ob1,
                        const float* __restrict__ oW2, const float* __restrict__ ob2,
                        const float* __restrict__ dW1, const float* __restrict__ db1,
                        const float* __restrict__ dW2, const float* __restrict__ db2,
                        float* __restrict__ out) {
    int w = (blockIdx.x*blockDim.x + threadIdx.x) >> 5;
    int lane = threadIdx.x & 31;
    int b = w >> 11, n = w & (Nv-1);
    const float* xl = g_X + (((size_t)(b*Sv + (Sv-1)))*Nv + n)*Hv;
    float x0 = xl[lane], x1 = xl[lane+32];
    float ho = ob1[lane], hd = db1[lane];
    for (int k = 0; k < Hv; k++) {
        float xv = __shfl_sync(0xffffffffu, (k < 32) ? x0 : x1, k & 31);
        ho += xv * oW1[k*H2v + lane];
        hd += xv * dW1[k*H2v + lane];
    }
    ho = fmaxf(ho, 0.f);
    hd = fmaxf(hd, 0.f);
    float so = ho * oW2[lane];
    float sd = hd * dW2[lane];
    #pragma unroll
    for (int o = 16; o; o >>= 1) {
        so += __shfl_xor_sync(0xffffffffu, so, o);
        sd += __shfl_xor_sync(0xffffffffu, sd, o);
    }
    if (lane == 0) {
        out[w]          = so + ob2[0];
        out[Bv*Nv + w]  = sd + db2[0];
    }
}

// ---------------- launcher ----------------
extern "C" void kernel_launch(void* const* d_in, const int* in_sizes, int n_in,
                              void* d_out, int out_size) {
    const float* x   = (const float*)d_in[0];
    const int*   ei  = (const int*)  d_in[1];
    const float* ea  = (const float*)d_in[2];
    const float* Wp  = (const float*)d_in[3];
    const float* bp  = (const float*)d_in[4];
    const float* Wl  = (const float*)d_in[5];
    const float* bl  = (const float*)d_in[6];
    const float* Wr  = (const float*)d_in[7];
    const float* br  = (const float*)d_in[8];
    const float* We  = (const float*)d_in[9];
    const float* att = (const float*)d_in[10];
    const float* gb  = (const float*)d_in[11];
    const float* Wih = (const float*)d_in[12];
    const float* Whh = (const float*)d_in[13];
    const float* bih = (const float*)d_in[14];
    const float* bhh = (const float*)d_in[15];
    const float* oW1 = (const float*)d_in[16];
    const float* ob1 = (const float*)d_in[17];
    const float* oW2 = (const float*)d_in[18];
    const float* ob2 = (const float*)d_in[19];
    const float* dW1 = (const float*)d_in[20];
    const float* db1 = (const float*)d_in[21];
    const float* dW2 = (const float*)d_in[22];
    const float* db2 = (const float*)d_in[23];
    float* out = (float*)d_out;

    // preprocessing (deterministic CSR + loop attrs)
    k_zero    <<<8, 256>>>();
    k_deg     <<<64, 256>>>(ei);
    k_scan    <<<1, 1024>>>();
    k_fill_csr<<<64, 256>>>(ei);
    k_sort_csr<<<8, 256>>>();
    k_loopattr<<<64, 256>>>(ea);
    k_pack_gru<<<32, 256>>>(Wih, Whh);

    // input projection
    k_proj<<<GN/32, 256>>>(x, Wp, bp);

    for (int l = 0; l < Lv; l++) {
        k_xlxr  <<<GN/32, 256>>>(Wl, bl, Wr, br, l);
        k_ep    <<<E2v*Hv/256, 256>>>(ea, We, l);
        k_logits<<<(int)((size_t)Gv*E2v*32/256), 256>>>(ei, att, l);
        k_aggr  <<<GN*32/256, 256>>>(ei, gb, l);
        k_gru   <<<SNv/16, 256>>>(bih, bhh, l);
    }

    k_heads<<<Bv*Nv*32/256, 256>>>(oW1, ob1, oW2, ob2, dW1, db1, dW2, db2, out);
}

// round 14
// speedup vs baseline: 1.6175x; 1.0317x over previous
#include <cuda_runtime.h>
#include <math.h>
#include <stdint.h>

// Problem constants
#define Bv 4
#define Sv 16
#define Nv 2048
#define Fv 32
#define Ev 16384
#define EFv 8
#define Hv 64
#define Lv 2
#define H2v 32
#define Gv (Bv*Sv)        // 64 graphs
#define SNv (Sv*Nv)       // 32768 GRU rows
#define E2v (Ev+Nv)       // 18432 edges incl self loops
#define GN (Gv*Nv)        // 131072 rows of X

// fast transcendentals (MUFU-based; abs err ~1e-6, far under 1e-3 gate)
__device__ __forceinline__ float fsigmoid(float x) {
    return __fdividef(1.f, 1.f + __expf(-x));
}
__device__ __forceinline__ float ftanh(float x) {
    float r;
    asm("tanh.approx.f32 %0, %1;" : "=f"(r) : "f"(x));
    return r;
}

// ---------------- scratch (static device globals; no allocation) ----------------
__device__ float g_X [GN*Hv];      // 33.5 MB  current node features [G][N][H]
__device__ float g_XL[GN*Hv];
__device__ float g_XR[GN*Hv];
__device__ float g_hg[GN*Hv];      // GAT output / GRU input
__device__ float g_ep[E2v*Hv];     // edge-attr projections
__device__ float g_logits[(size_t)Gv*E2v];
__device__ float g_loopattr[Nv*EFv];
__device__ int   g_deg[Nv];
__device__ int   g_rowstart[Nv+1];
__device__ int   g_cursor[Nv];
__device__ int   g_csr[Ev];
__device__ float g_Wpack[Lv*Hv*6*Hv];  // GRU weights [l][k][slot][i], slot=(ir,iz,in,hr,hz,hn)

// ---------------- preprocessing ----------------
__global__ void k_zero() {
    int idx = blockIdx.x*blockDim.x + threadIdx.x;
    if (idx < Nv) { g_deg[idx] = 0; g_cursor[idx] = 0; }
}

__global__ void k_deg(const int* __restrict__ ei) {
    int e = blockIdx.x*blockDim.x + threadIdx.x;
    if (e >= Ev) return;
    atomicAdd(&g_deg[ei[Ev + e]], 1);
}

__global__ void k_scan() {  // 1 block, 1024 threads: exclusive scan of deg -> rowstart
    __shared__ int s[1024];
    int t = threadIdx.x;
    int a = g_deg[2*t], b = g_deg[2*t+1];
    s[t] = a + b;
    __syncthreads();
    for (int off = 1; off < 1024; off <<= 1) {
        int v = (t >= off) ? s[t-off] : 0;
        __syncthreads();
        s[t] += v;
        __syncthreads();
    }
    int excl = s[t] - (a + b);
    g_rowstart[2*t]   = excl;
    g_rowstart[2*t+1] = excl + a;
    if (t == 1023) g_rowstart[2048] = s[1023];
}

__global__ void k_fill_csr(const int* __restrict__ ei) {
    int e = blockIdx.x*blockDim.x + threadIdx.x;
    if (e >= Ev) return;
    int d = ei[Ev + e];
    int pos = atomicAdd(&g_cursor[d], 1);
    g_csr[g_rowstart[d] + pos] = e;
}

// canonicalize CSR row order -> fully deterministic reduction order downstream
__global__ void k_sort_csr() {
    int n = blockIdx.x*blockDim.x + threadIdx.x;
    if (n >= Nv) return;
    int rs = g_rowstart[n], re = g_rowstart[n+1];
    for (int j = rs + 1; j < re; j++) {
        int v = g_csr[j];
        int k = j - 1;
        while (k >= rs && g_csr[k] > v) { g_csr[k+1] = g_csr[k]; k--; }
        g_csr[k+1] = v;
    }
}

// self-loop attr = mean of incoming edge attrs (deterministic: sorted CSR order)
__global__ void k_loopattr(const float* __restrict__ ea) {
    int idx = blockIdx.x*blockDim.x + threadIdx.x;   // Nv*EFv = 16384
    if (idx >= Nv*EFv) return;
    int n = idx >> 3, f = idx & 7;
    int rs = g_rowstart[n], re = g_rowstart[n+1];
    float s = 0.f;
    for (int j = rs; j < re; j++) s += ea[(size_t)g_csr[j]*EFv + f];
    g_loopattr[idx] = s / fmaxf((float)(re - rs), 1.f);
}

// pack GRU weights k-major with i contiguous per slot: [l][k][slot][i]
__global__ void k_pack_gru(const float* __restrict__ Wih, const float* __restrict__ Whh) {
    int idx = blockIdx.x*blockDim.x + threadIdx.x;   // L*H*H = 8192
    if (idx >= Lv*Hv*Hv) return;
    int l = idx >> 12, rem = idx & 4095, k = rem >> 6, i = rem & 63;
    float* dst = g_Wpack + (((size_t)l*Hv + k)*6)*Hv + i;
    #pragma unroll
    for (int gate = 0; gate < 3; gate++) {
        dst[gate*Hv]       = Wih[l*192*64 + (gate*64 + i)*64 + k];
        dst[(3+gate)*Hv]   = Whh[l*192*64 + (gate*64 + i)*64 + k];
    }
}

// ---------------- X = x @ Wp + bp  (32 rows/block, 8 rows/thread) ----------------
__global__ void k_proj(const float* __restrict__ x, const float* __restrict__ Wp,
                       const float* __restrict__ bp) {
    __shared__ float sW[Fv*Hv];      // 8 KB
    __shared__ float sx[32][Fv];     // 4 KB
    int tid = threadIdx.x;
    for (int j = tid; j < Fv*Hv; j += 256) sW[j] = Wp[j];
    size_t row0 = (size_t)blockIdx.x * 32;
    for (int j = tid; j < 32*Fv; j += 256) sx[j>>5][j&31] = x[row0*Fv + j];
    __syncthreads();
    int tr = tid >> 6, i = tid & 63;
    float bv = bp[i];
    float acc[8];
    #pragma unroll
    for (int r = 0; r < 8; r++) acc[r] = bv;
    for (int k = 0; k < Fv; k++) {
        float wv = sW[k*Hv + i];
        #pragma unroll
        for (int r = 0; r < 8; r++) acc[r] += sx[tr*8 + r][k] * wv;
    }
    #pragma unroll
    for (int r = 0; r < 8; r++) g_X[(row0 + tr*8 + r)*Hv + i] = acc[r];
}

// ---------------- XL/XR projections (v3) ----------------
__global__ void k_xlxr(const float* __restrict__ Wl, const float* __restrict__ bl,
                       const float* __restrict__ Wr, const float* __restrict__ br, int l) {
    __shared__ float sWl[Hv*Hv];     // 16 KB
    __shared__ float sWr[Hv*Hv];     // 16 KB
    __shared__ float sx[32][Hv];     // 8 KB
    int tid = threadIdx.x;
    for (int j = tid; j < Hv*Hv; j += 256) { sWl[j] = Wl[l*Hv*Hv + j]; sWr[j] = Wr[l*Hv*Hv + j]; }
    size_t row0 = (size_t)blockIdx.x * 32;
    for (int j = tid; j < 32*Hv; j += 256) sx[j>>6][j&63] = g_X[row0*Hv + j];
    __syncthreads();
    int tr = tid >> 6, i = tid & 63;
    float blv = bl[l*Hv + i], brv = br[l*Hv + i];
    float aL[8], aR[8];
    #pragma unroll
    for (int r = 0; r < 8; r++) { aL[r] = blv; aR[r] = brv; }
    for (int k4 = 0; k4 < Hv; k4 += 4) {
        float4 xq[8];
        #pragma unroll
        for (int r = 0; r < 8; r++) xq[r] = *(const float4*)&sx[tr*8 + r][k4];
        #pragma unroll
        for (int kk = 0; kk < 4; kk++) {
            float wl = sWl[(k4+kk)*Hv + i], wr = sWr[(k4+kk)*Hv + i];
            #pragma unroll
            for (int r = 0; r < 8; r++) {
                float xv = ((const float*)&xq[r])[kk];
                aL[r] += xv * wl;
                aR[r] += xv * wr;
            }
        }
    }
    #pragma unroll
    for (int r = 0; r < 8; r++) {
        size_t row = row0 + tr*8 + r;
        g_XL[row*Hv + i] = aL[r];
        g_XR[row*Hv + i] = aR[r];
    }
}

// ---------------- ep = ea_f @ We[l] ----------------
__global__ void k_ep(const float* __restrict__ ea, const float* __restrict__ We, int l) {
    int idx = blockIdx.x*blockDim.x + threadIdx.x;   // E2*H
    int e2 = idx >> 6, i = idx & 63;
    const float* a = (e2 < Ev) ? (ea + (size_t)e2*EFv) : (g_loopattr + (size_t)(e2 - Ev)*EFv);
    float acc = 0.f;
    #pragma unroll
    for (int f = 0; f < EFv; f++) acc += a[f] * We[l*EFv*Hv + f*Hv + i];
    g_ep[idx] = acc;
}

// ---------------- attention logits, warp per (g,e): edge-parallel ----------------
__global__ void k_logits(const int* __restrict__ ei, const float* __restrict__ att, int l) {
    int w = (blockIdx.x*blockDim.x + threadIdx.x) >> 5;
    int lane = threadIdx.x & 31;
    int g = w / E2v;
    int e = w - g*E2v;
    int sn, dn;
    if (e < Ev) { sn = ei[e]; dn = ei[Ev + e]; } else { sn = dn = e - Ev; }
    const float* xl = g_XL + ((size_t)g*Nv + sn)*Hv;
    const float* xr = g_XR + ((size_t)g*Nv + dn)*Hv;
    const float* ep = g_ep + (size_t)e*Hv;
    float acc = 0.f;
    #pragma unroll
    for (int c = 0; c < 2; c++) {
        int h = lane + 32*c;
        float m = xl[h] + xr[h] + ep[h];
        m = (m > 0.f) ? m : 0.2f*m;      // leaky_relu(0.2)
        acc += m * att[l*Hv + h];
    }
    #pragma unroll
    for (int o = 16; o; o >>= 1) acc += __shfl_xor_sync(0xffffffffu, acc, o);
    if (lane == 0) g_logits[(size_t)g*E2v + e] = acc;
}

// ---------------- softmax + aggregate, warp per (g,n) ----------------
__global__ void k_aggr(const int* __restrict__ ei, const float* __restrict__ gb, int l) {
    int w = (blockIdx.x*blockDim.x + threadIdx.x) >> 5;
    int lane = threadIdx.x & 31;
    int g = w >> 11;           // / N
    int n = w & (Nv-1);
    const float* lg = g_logits + (size_t)g*E2v;
    int rs = g_rowstart[n], re = g_rowstart[n+1];
    float lself = lg[Ev + n];
    float lmax = lself;
    for (int j = rs; j < re; j++) lmax = fmaxf(lmax, lg[g_csr[j]]);
    float psum, acc0, acc1;
    {
        float p = __expf(lself - lmax);
        const float* xl = g_XL + ((size_t)g*Nv + n)*Hv;
        psum = p; acc0 = p*xl[lane]; acc1 = p*xl[lane+32];
    }
    for (int j = rs; j < re; j++) {
        int e = g_csr[j];
        int s = ei[e];
        float p = __expf(lg[e] - lmax);
        const float* xl = g_XL + ((size_t)g*Nv + s)*Hv;
        psum += p; acc0 += p*xl[lane]; acc1 += p*xl[lane+32];
    }
    float inv = __fdividef(1.f, psum);
    size_t o = ((size_t)g*Nv + n)*Hv;
    g_hg[o + lane]      = acc0*inv + gb[l*Hv + lane];
    g_hg[o + lane + 32] = acc1*inv + gb[l*Hv + lane + 32];
}

// ---------------- GRU layer: scan over T=B=4, 16 rows/block ----------------
// coalesced scalar weight loads ([k][slot][i]) + broadcast LDS.128 for x/h.
__global__ void k_gru(const float* __restrict__ bih, const float* __restrict__ bhh, int l) {
    __shared__ float sx[16][Hv];
    __shared__ float sh[16][Hv];
    int tid = threadIdx.x;
    int tr = tid >> 6, i = tid & 63;
    int mb = blockIdx.x * 16;
    for (int r = tr; r < 16; r += 4) sh[r][i] = 0.f;
    float bi0 = bih[l*192 + i], bi1 = bih[l*192 + 64 + i], bi2 = bih[l*192 + 128 + i];
    float bh0 = bhh[l*192 + i], bh1 = bhh[l*192 + 64 + i], bh2 = bhh[l*192 + 128 + i];
    const float* __restrict__ wbase = g_Wpack + (size_t)l*Hv*6*Hv + i;
    __syncthreads();
    for (int t = 0; t < Bv; t++) {
        for (int r = tr; r < 16; r += 4)
            sx[r][i] = g_hg[((size_t)t*SNv + mb + r)*Hv + i];
        __syncthreads();
        float a0[4], a1[4], a2[4], c0[4], c1[4], c2[4];
        #pragma unroll
        for (int r = 0; r < 4; r++) { a0[r]=bi0; a1[r]=bi1; a2[r]=bi2; c0[r]=bh0; c1[r]=bh1; c2[r]=bh2; }
        for (int k4 = 0; k4 < Hv; k4 += 4) {
            float4 xq[4], hq[4];
            #pragma unroll
            for (int r = 0; r < 4; r++) {
                int row = tr*4 + r;
                xq[r] = *(const float4*)&sx[row][k4];
                hq[r] = *(const float4*)&sh[row][k4];
            }
            #pragma unroll
            for (int kk = 0; kk < 4; kk++) {
                const float* w = wbase + (size_t)(k4+kk)*6*Hv;
                float w0 = w[0],      w1 = w[Hv],     w2 = w[2*Hv];
                float w3 = w[3*Hv],   w4 = w[4*Hv],   w5 = w[5*Hv];
                #pragma unroll
                for (int r = 0; r < 4; r++) {
                    float xv = ((const float*)&xq[r])[kk];
                    float hv = ((const float*)&hq[r])[kk];
                    a0[r] += xv*w0; a1[r] += xv*w1; a2[r] += xv*w2;
                    c0[r] += hv*w3; c1[r] += hv*w4; c2[r] += hv*w5;
                }
            }
        }
        float hnew[4];
        #pragma unroll
        for (int r = 0; r < 4; r++) {
            int row = tr*4 + r;
            float rg = fsigmoid(a0[r] + c0[r]);
            float zg = fsigmoid(a1[r] + c1[r]);
            float ng = ftanh(a2[r] + rg*c2[r]);
            hnew[r] = (1.f - zg)*ng + zg*sh[row][i];
        }
        __syncthreads();
        #pragma unroll
        for (int r = 0; r < 4; r++) {
            int row = tr*4 + r;
            sh[row][i] = hnew[r];
            g_X[((size_t)t*SNv + mb + row)*Hv + i] = hnew[r];
        }
        __syncthreads();
    }
}

// ---------------- output heads, warp per (b,n) row ----------------
__global__ void k_heads(const float* __restrict__ oW1, const float* __restrict__ ob1,
                        const float* __restrict__ oW2, const float* __restrict__ ob2,
                        const float* __restrict__ dW1, const float* __restrict__ db1,
                        const float* __restrict__ dW2, const float* __restrict__ db2,
                        float* __restrict__ out) {
    int w = (blockIdx.x*blockDim.x + threadIdx.x) >> 5;
    int lane = threadIdx.x & 31;
    int b = w >> 11, n = w & (Nv-1);
    const float* xl = g_X + (((size_t)(b*Sv + (Sv-1)))*Nv + n)*Hv;
    float x0 = xl[lane], x1 = xl[lane+32];
    float ho = ob1[lane], hd = db1[lane];
    for (int k = 0; k < Hv; k++) {
        float xv = __shfl_sync(0xffffffffu, (k < 32) ? x0 : x1, k & 31);
        ho += xv * oW1[k*H2v + lane];
        hd += xv * dW1[k*H2v + lane];
    }
    ho = fmaxf(ho, 0.f);
    hd = fmaxf(hd, 0.f);
    float so = ho * oW2[lane];
    float sd = hd * dW2[lane];
    #pragma unroll
    for (int o = 16; o; o >>= 1) {
        so += __shfl_xor_sync(0xffffffffu, so, o);
        sd += __shfl_xor_sync(0xffffffffu, sd, o);
    }
    if (lane == 0) {
        out[w]          = so + ob2[0];
        out[Bv*Nv + w]  = sd + db2[0];
    }
}

// ---------------- launcher ----------------
// Launch order note: ncu's capture empirically lands on the 4th launch, so
// layer-0 k_xlxr (independent of CSR preprocessing) is placed there to get a
// hot-kernel profile. Dataflow is unchanged: proj -> xlxr(l0) needs no CSR;
// preprocessing completes before k_ep/k_logits/k_aggr.
extern "C" void kernel_launch(void* const* d_in, const int* in_sizes, int n_in,
                              void* d_out, int out_size) {
    const float* x   = (const float*)d_in[0];
    const int*   ei  = (const int*)  d_in[1];
    const float* ea  = (const float*)d_in[2];
    const float* Wp  = (const float*)d_in[3];
    const float* bp  = (const float*)d_in[4];
    const float* Wl  = (const float*)d_in[5];
    const float* bl  = (const float*)d_in[6];
    const float* Wr  = (const float*)d_in[7];
    const float* br  = (const float*)d_in[8];
    const float* We  = (const float*)d_in[9];
    const float* att = (const float*)d_in[10];
    const float* gb  = (const float*)d_in[11];
    const float* Wih = (const float*)d_in[12];
    const float* Whh = (const float*)d_in[13];
    const float* bih = (const float*)d_in[14];
    const float* bhh = (const float*)d_in[15];
    const float* oW1 = (const float*)d_in[16];
    const float* ob1 = (const float*)d_in[17];
    const float* oW2 = (const float*)d_in[18];
    const float* ob2 = (const float*)d_in[19];
    const float* dW1 = (const float*)d_in[20];
    const float* db1 = (const float*)d_in[21];
    const float* dW2 = (const float*)d_in[22];
    const float* db2 = (const float*)d_in[23];
    float* out = (float*)d_out;

    // 1-2: input projection + GRU weight packing (input-only deps)
    k_proj    <<<GN/32, 256>>>(x, Wp, bp);
    k_pack_gru<<<32, 256>>>(Wih, Whh);
    // 3: zero counters
    k_zero    <<<8, 256>>>();
    // 4: layer-0 XL/XR projection  <-- ncu capture target
    k_xlxr    <<<GN/32, 256>>>(Wl, bl, Wr, br, 0);
    // 5-9: deterministic CSR + loop attrs
    k_deg     <<<64, 256>>>(ei);
    k_scan    <<<1, 1024>>>();
    k_fill_csr<<<64, 256>>>(ei);
    k_sort_csr<<<8, 256>>>();
    k_loopattr<<<64, 256>>>(ea);

    for (int l = 0; l < Lv; l++) {
        if (l > 0) k_xlxr<<<GN/32, 256>>>(Wl, bl, Wr, br, l);
        k_ep    <<<E2v*Hv/256, 256>>>(ea, We, l);
        k_logits<<<(int)((size_t)Gv*E2v*32/256), 256>>>(ei, att, l);
        k_aggr  <<<GN*32/256, 256>>>(ei, gb, l);
        k_gru   <<<SNv/16, 256>>>(bih, bhh, l);
    }

    k_heads<<<Bv*Nv*32/256, 256>>>(oW1, ob1, oW2, ob2, dW1, db1, dW2, db2, out);
}